// round 11
// baseline (speedup 1.0000x reference)
#include <cuda_runtime.h>
#include <cstdint>

#define G  256
#define NV 512
#define NE 4096
#define FI 64
#define FO 64
#define NC 16
#define KFLAT (NV*FO)      // 32768

__device__ float g_h [(size_t)G*NV*FO];          // 33.5 MB
__device__ float g_part[(size_t)G*512*NC];       // 8 MB: [g][kseg][c]

#define FMA2(acc, a, b) asm("fma.rn.f32x2 %0, %1, %2, %0;" : "+l"(acc) : "l"(a), "l"(b))

// ---- fused-kernel smem layout (bytes) ---------------------------------------------
#define SM_XW    0                                  // float[NV*FO]  131072 (x then xw, in place)
#define SM_W     (SM_XW   + NV*FO*4)                // float[FO*FI]   16384 (swizzled)
#define SM_DINV  (SM_W    + FO*FI*4)                // float[NV]       2048
#define SM_ROWP  (SM_DINV + NV*4)                   // int[NV+1]       2052
#define SM_WTMP  ((SM_ROWP + (NV+1)*4 + 15) & ~15)  // int[16]
#define SM_OFFS  ((SM_WTMP + 64 + 15) & ~15)        // int[NV]         2048
#define SM_ESH   ((SM_OFFS + NV*4 + 15) & ~15)      // ull[NE]        32768 (packed src|nrm)
#define SMEM_TOT (SM_ESH + NE*8)                    // ~186.5 KB

// =====================================================================================
// Fused per-graph kernel, 1024 threads (32 warps).
//   1) zero offs + stage swizzled W
//   2) histogram (edges kept in regs) + stage x into xw buffer
//   3) dinv + block scan -> rowptr
//   4) scatter packed (src, nrm) edge records sorted by target
//   5) GEMM xw = x@W^T IN PLACE: warp w owns rows [8w,8w+8) U [256+8w,..+8);
//      all readers of a row-block are in the owning warp; __syncwarp before stores.
//      Thread tile 8n x 2o, packed f32x2, XOR-swizzled b (conflict-free LDS.64).
//   6) gather: warp per node (16/warp), lane owns 2 feats; one broadcast LDS.64
//      per edge record; +bias, ReLU -> g_h.
// =====================================================================================
__global__ __launch_bounds__(1024, 1) void k_fused(const float* __restrict__ x,
                                                   const float* __restrict__ W,
                                                   const int* __restrict__ eidx,
                                                   const float* __restrict__ cbias) {
    extern __shared__ char sm[];
    float* xw_s  = (float*)(sm + SM_XW);
    float* w_s   = (float*)(sm + SM_W);
    float* dinv  = (float*)(sm + SM_DINV);
    int*   rowptr= (int*)  (sm + SM_ROWP);
    int*   wtmp  = (int*)  (sm + SM_WTMP);
    int*   offs  = (int*)  (sm + SM_OFFS);
    unsigned long long* esh = (unsigned long long*)(sm + SM_ESH);

    const int g    = blockIdx.x;
    const int tid  = threadIdx.x;
    const int lane = tid & 31, wrp = tid >> 5;
    const int* srce = eidx + (size_t)g*2*NE;
    const int* tgte = srce + NE;

    // ---- phase 0: zero counters + stage W (pair-granular XOR swizzle) ----
    if (tid < NV) offs[tid] = 0;
    for (int i = tid; i < FO*FI/2; i += 1024) {
        int o  = i >> 5;
        int fp = (i & 31) * 2;
        int fs = fp ^ (2*((o >> 1) & 15));
        *(unsigned long long*)&w_s[o*64 + fs] =
            *(const unsigned long long*)&W[o*FI + fp];
    }
    __syncthreads();

    // ---- phase 1: histogram (edges -> regs) + stage x into xw buffer ----
    int es[4], ec[4];
#pragma unroll
    for (int q = 0; q < 4; q++) {
        int e = tid + q*1024;
        es[q] = srce[e];
        ec[q] = tgte[e];
        atomicAdd(&offs[ec[q]], 1);
    }
    {
        const float4* xg4 = (const float4*)(x + (size_t)g*NV*FI);
        float4* xs4 = (float4*)xw_s;
#pragma unroll
        for (int q = 0; q < 8; q++)
            xs4[tid + q*1024] = xg4[tid + q*1024];
    }
    __syncthreads();

    // ---- phase 2: dinv + block exclusive scan (warps 0..15 hold counts) ----
    int cnt = 0;
    if (tid < NV) {
        cnt = offs[tid];
        dinv[tid] = rsqrtf((float)(cnt + 1));   // +1 self-loop
    }
    int v = cnt;
#pragma unroll
    for (int d = 1; d < 32; d <<= 1) {
        int t = __shfl_up_sync(0xffffffffu, v, d);
        if (lane >= d) v += t;
    }
    if (lane == 31 && wrp < 16) wtmp[wrp] = v;
    __syncthreads();
    if (wrp == 0) {
        int wv = (lane < 16) ? wtmp[lane] : 0;
#pragma unroll
        for (int d = 1; d < 16; d <<= 1) {
            int t = __shfl_up_sync(0xffffffffu, wv, d);
            if (lane >= d) wv += t;
        }
        if (lane < 16) wtmp[lane] = wv;
    }
    __syncthreads();
    if (tid < NV) {
        const int base = (wrp > 0) ? wtmp[wrp-1] : 0;
        const int excl = base + (v - cnt);
        rowptr[tid] = excl;
        offs[tid]   = excl;
        if (tid == 0) rowptr[NV] = NE;
    }
    __syncthreads();

    // ---- phase 3: scatter packed (src, nrm) sorted by target ----
#pragma unroll
    for (int q = 0; q < 4; q++) {
        int s = es[q], c = ec[q];
        int p = atomicAdd(&offs[c], 1);
        float nrm = dinv[s] * dinv[c];
        esh[p] = ((unsigned long long)__float_as_uint(nrm) << 32) | (unsigned)s;
    }
    // no barrier needed before GEMM (GEMM touches xw/w only); esh barrier folded below

    // ---- phase 4: GEMM in place. warp owns rows [8*wrp, +8) and [256+8*wrp, +8) ----
    const int ob = 2*lane, sw = 2*(lane & 15);
#pragma unroll 1
    for (int t = 0; t < 2; t++) {
        const int rb = t*256 + wrp*8;

        unsigned long long acc[8][2];
#pragma unroll
        for (int i = 0; i < 8; i++) { acc[i][0] = 0ull; acc[i][1] = 0ull; }

#pragma unroll
        for (int f = 0; f < 64; f += 4) {
            unsigned long long b0[2], b1[2];
#pragma unroll
            for (int j = 0; j < 2; j++) {
                b0[j] = *(const unsigned long long*)&w_s[(ob+j)*64 + ( f      ^ sw)];
                b1[j] = *(const unsigned long long*)&w_s[(ob+j)*64 + ((f + 2) ^ sw)];
            }
#pragma unroll
            for (int i = 0; i < 8; i++) {
                ulonglong2 a2 = *(const ulonglong2*)&xw_s[(rb+i)*64 + f];
                FMA2(acc[i][0], a2.x, b0[0]);
                FMA2(acc[i][1], a2.x, b0[1]);
                FMA2(acc[i][0], a2.y, b1[0]);
                FMA2(acc[i][1], a2.y, b1[1]);
            }
        }
        __syncwarp();                       // all lanes done reading rows before stores
#pragma unroll
        for (int i = 0; i < 8; i++) {
            float2 o2;
            o2.x = __uint_as_float((unsigned)(acc[i][0] & 0xffffffffull))
                 + __uint_as_float((unsigned)(acc[i][0] >> 32));
            o2.y = __uint_as_float((unsigned)(acc[i][1] & 0xffffffffull))
                 + __uint_as_float((unsigned)(acc[i][1] >> 32));
            *(float2*)&xw_s[(rb+i)*64 + ob] = o2;
        }
    }
    __syncthreads();                        // xw complete + esh/scatter complete

    // ---- phase 5: gather. warp per node (16/warp), lane owns 2 feats ----
    const float bias0 = cbias[2*lane];
    const float bias1 = cbias[2*lane + 1];
    for (int n = wrp*16; n < wrp*16 + 16; n++) {
        const float d = dinv[n];
        float2 xv = *(const float2*)&xw_s[n*FO + 2*lane];
        float a0 = xv.x * (d*d);
        float a1 = xv.y * (d*d);
        int j = rowptr[n];
        const int end = rowptr[n+1];
        for (; j + 4 <= end; j += 4) {
            unsigned long long e0 = esh[j],   e1 = esh[j+1];
            unsigned long long e2 = esh[j+2], e3 = esh[j+3];
            float2 m0 = *(const float2*)&xw_s[(int)(e0 & 0xffffffffu)*FO + 2*lane];
            float2 m1 = *(const float2*)&xw_s[(int)(e1 & 0xffffffffu)*FO + 2*lane];
            float2 m2 = *(const float2*)&xw_s[(int)(e2 & 0xffffffffu)*FO + 2*lane];
            float2 m3 = *(const float2*)&xw_s[(int)(e3 & 0xffffffffu)*FO + 2*lane];
            float w0 = __uint_as_float((unsigned)(e0 >> 32));
            float w1 = __uint_as_float((unsigned)(e1 >> 32));
            float w2 = __uint_as_float((unsigned)(e2 >> 32));
            float w3 = __uint_as_float((unsigned)(e3 >> 32));
            a0 = fmaf(m0.x, w0, a0);  a1 = fmaf(m0.y, w0, a1);
            a0 = fmaf(m1.x, w1, a0);  a1 = fmaf(m1.y, w1, a1);
            a0 = fmaf(m2.x, w2, a0);  a1 = fmaf(m2.y, w2, a1);
            a0 = fmaf(m3.x, w3, a0);  a1 = fmaf(m3.y, w3, a1);
        }
        for (; j < end; j++) {
            unsigned long long e0 = esh[j];
            float2 m = *(const float2*)&xw_s[(int)(e0 & 0xffffffffu)*FO + 2*lane];
            float w = __uint_as_float((unsigned)(e0 >> 32));
            a0 = fmaf(m.x, w, a0);
            a1 = fmaf(m.y, w, a1);
        }
        float2 o;
        o.x = fmaxf(a0 + bias0, 0.f);
        o.y = fmaxf(a1 + bias1, 0.f);
        *(float2*)&g_h[((size_t)g*NV + n)*FO + 2*lane] = o;
    }
}

// =====================================================================================
// K3: logits split-K, weight-stationary. grid(16 graph-tiles, 64 k-chunks), 256 thr.
// =====================================================================================
__global__ __launch_bounds__(256) void k_lin(const float* __restrict__ lw) {
    const int bx = blockIdx.x;
    const int by = blockIdx.y;
    const int tid = threadIdx.x;
    const int lane = tid & 31, wrp = tid >> 5;
    const int c  = lane & 15;
    const int kh = lane >> 4;
    const int kbase = by*512 + wrp*64 + kh*32;
    const int seg = by*8 + wrp;

    unsigned long long wreg[16];
    const float* wp = lw + (size_t)c*KFLAT + kbase;
#pragma unroll
    for (int p = 0; p < 16; p++)
        wreg[p] = *(const unsigned long long*)&wp[2*p];

    for (int gi = 0; gi < 16; gi++) {
        const int g = bx*16 + gi;
        const float* hp = g_h + (size_t)g*KFLAT + kbase;
        unsigned long long acc0 = 0ull, acc1 = 0ull;
#pragma unroll
        for (int p = 0; p < 4; p++) {
            ulonglong2 ha = *(const ulonglong2*)&hp[8*p];
            ulonglong2 hb = *(const ulonglong2*)&hp[8*p + 4];
            FMA2(acc0, ha.x, wreg[4*p    ]);
            FMA2(acc1, ha.y, wreg[4*p + 1]);
            FMA2(acc0, hb.x, wreg[4*p + 2]);
            FMA2(acc1, hb.y, wreg[4*p + 3]);
        }
        float s = __uint_as_float((unsigned)(acc0 & 0xffffffffull))
                + __uint_as_float((unsigned)(acc0 >> 32))
                + __uint_as_float((unsigned)(acc1 & 0xffffffffull))
                + __uint_as_float((unsigned)(acc1 >> 32));
        s += __shfl_xor_sync(0xffffffffu, s, 16);
        if (kh == 0)
            g_part[((size_t)g*512 + seg)*NC + c] = s;
    }
}

// =====================================================================================
// K4: one block per graph. float4 partial sums, smem tree, + bias, log_softmax.
// =====================================================================================
__global__ __launch_bounds__(256) void k_sm(const float* __restrict__ lbias,
                                            float* __restrict__ out) {
    __shared__ float red[64][16];
    const int g = blockIdx.x;
    const int t = threadIdx.x;
    const int quad = t & 3, sg = t >> 2;

    const float4* pp4 = (const float4*)(g_part + (size_t)g*512*NC);
    float4 acc = make_float4(0.f, 0.f, 0.f, 0.f);
#pragma unroll
    for (int s8 = 0; s8 < 8; s8++) {
        float4 v = pp4[(sg*8 + s8)*4 + quad];
        acc.x += v.x; acc.y += v.y; acc.z += v.z; acc.w += v.w;
    }
    *(float4*)&red[sg][quad*4] = acc;
    __syncthreads();

    if (t < 16) {
        float tot = lbias[t];
#pragma unroll 8
        for (int s = 0; s < 64; s++) tot += red[s][t];

        float m = tot;
#pragma unroll
        for (int d = 8; d >= 1; d >>= 1)
            m = fmaxf(m, __shfl_xor_sync(0x0000ffffu, m, d));
        float e = expf(tot - m);
#pragma unroll
        for (int d = 8; d >= 1; d >>= 1)
            e += __shfl_xor_sync(0x0000ffffu, e, d);

        out[(size_t)g*NC + t] = (tot - m) - logf(e);
    }
}

// =====================================================================================
extern "C" void kernel_launch(void* const* d_in, const int* in_sizes, int n_in,
                              void* d_out, int out_size) {
    const float* x  = (const float*)d_in[0];   // [G,NV,FI]
    const int*   ei = (const int*)  d_in[1];   // [G,2,NE]
    const float* cw = (const float*)d_in[2];   // [FO,FI]
    const float* cb = (const float*)d_in[3];   // [FO]
    const float* lw = (const float*)d_in[4];   // [NC,KFLAT]
    const float* lb = (const float*)d_in[5];   // [NC]
    float* out = (float*)d_out;                // [G,NC]

    (void)in_sizes; (void)n_in; (void)out_size;

    cudaFuncSetAttribute(k_fused, cudaFuncAttributeMaxDynamicSharedMemorySize, SMEM_TOT);

    k_fused<<<G, 1024, SMEM_TOT>>>(x, cw, ei, cb);
    k_lin  <<<dim3(16, 64), 256>>>(lw);
    k_sm   <<<G, 256>>>(lb, out);
}

// round 16
// speedup vs baseline: 1.6166x; 1.6166x over previous
#include <cuda_runtime.h>
#include <cstdint>

#define G  256
#define NV 512
#define NE 4096
#define FI 64
#define FO 64
#define NC 16
#define KFLAT (NV*FO)      // 32768

__device__ float g_h [(size_t)G*NV*FO];          // 33.5 MB
__device__ float g_part[(size_t)G*512*NC];       // 8 MB: [g][kseg][c]

#define FMA2(acc, a, b) asm("fma.rn.f32x2 %0, %1, %2, %0;" : "+l"(acc) : "l"(a), "l"(b))

// ---- fused-kernel smem layout (bytes) ----------------------------------------------
// Persistent: xw (result), w (swizzled weights), dinv, rowptr, wtmp.
// UNION: GEMM phase -> x staging (64 KB); CSR phase -> offs + packed edge records.
#define SM_XW    0                          // float[NV*FO]   131072
#define SM_W     (SM_XW   + NV*FO*4)        // float[FO*FI]    16384
#define SM_DINV  (SM_W    + FO*FI*4)        // float[NV]        2048
#define SM_ROWP  (SM_DINV + NV*4)           // int[NV+1]        2052
#define SM_WTMP  ((SM_ROWP + (NV+1)*4 + 15) & ~15)   // int[16]
#define SM_UNION ((SM_WTMP + 64 + 15) & ~15)
#define SM_XSTG  SM_UNION                   // float[256*FI]   65536 (GEMM phase)
#define SM_OFFS  SM_UNION                   // int[NV]          2048 (CSR phase)
#define SM_ESH   ((SM_OFFS + NV*4 + 7) & ~7)// ull[NE]         32768 (packed nrm|src)
#define SMEM_TOT (SM_UNION + 256*FI*4)      // ~217 KB

// =====================================================================================
// Fused per-graph kernel, 1024 threads (32 warps) — R7 structure.
//   A) GEMM xw = x@W^T in smem: 2 phases x 256 rows, thread tile 8n x 2o,
//      packed f32x2 over f; a broadcast; b XOR-swizzled (2-cycle floor LDS.64).
//   B) CSR build in union region; scatter writes PACKED (nrm,src) 8B records.
//   C) Gather: warp per node (16/warp), lane owns 2 feats; one broadcast LDS.64
//      per edge record + one 2-way LDS.64 message load; +bias, ReLU -> g_h.
// =====================================================================================
__global__ __launch_bounds__(1024, 1) void k_fused(const float* __restrict__ x,
                                                   const float* __restrict__ W,
                                                   const int* __restrict__ eidx,
                                                   const float* __restrict__ cbias) {
    extern __shared__ char sm[];
    float* xw_s  = (float*)(sm + SM_XW);
    float* w_s   = (float*)(sm + SM_W);
    float* dinv  = (float*)(sm + SM_DINV);
    int*   rowptr= (int*)  (sm + SM_ROWP);
    int*   wtmp  = (int*)  (sm + SM_WTMP);
    float* xstg  = (float*)(sm + SM_XSTG);
    int*   offs  = (int*)  (sm + SM_OFFS);
    unsigned long long* esh = (unsigned long long*)(sm + SM_ESH);

    const int g    = blockIdx.x;
    const int tid  = threadIdx.x;
    const int lane = tid & 31, wrp = tid >> 5;
    const int* srce = eidx + (size_t)g*2*NE;
    const int* tgte = srce + NE;

    // ---- load W with pair-granular XOR swizzle ----
    for (int i = tid; i < FO*FI/2; i += 1024) {
        int o  = i >> 5;
        int fp = (i & 31) * 2;
        int fs = fp ^ (2*((o >> 1) & 15));
        *(unsigned long long*)&w_s[o*64 + fs] =
            *(const unsigned long long*)&W[o*64 + fp];
    }

    // ---- GEMM: 2 phases of 256 nodes ----
    const int tx = tid & 31;          // o-group (2 outs)
    const int ny = tid >> 5;          // n-group (8 rows) == warp id -> a broadcast
    const int nb = ny * 8, ob = tx * 2, sw = 2 * (tx & 15);

#pragma unroll 1
    for (int p = 0; p < 2; p++) {
        __syncthreads();              // union/xstg reuse boundary
        const float4* xg4 = (const float4*)(x + ((size_t)g*NV + p*256) * FI);
        float4* xs4 = (float4*)xstg;
        for (int i = tid; i < 256*FI/4; i += 1024) xs4[i] = xg4[i];
        __syncthreads();

        unsigned long long acc[8][2];
#pragma unroll
        for (int i = 0; i < 8; i++) { acc[i][0] = 0ull; acc[i][1] = 0ull; }

#pragma unroll
        for (int f = 0; f < 64; f += 4) {
            unsigned long long b0[2], b1[2];
#pragma unroll
            for (int j = 0; j < 2; j++) {
                b0[j] = *(const unsigned long long*)&w_s[(ob+j)*64 + ( f      ^ sw)];
                b1[j] = *(const unsigned long long*)&w_s[(ob+j)*64 + ((f + 2) ^ sw)];
            }
#pragma unroll
            for (int i = 0; i < 8; i++) {
                ulonglong2 a2 = *(const ulonglong2*)&xstg[(nb+i)*64 + f];
                FMA2(acc[i][0], a2.x, b0[0]);
                FMA2(acc[i][1], a2.x, b0[1]);
                FMA2(acc[i][0], a2.y, b1[0]);
                FMA2(acc[i][1], a2.y, b1[1]);
            }
        }
#pragma unroll
        for (int i = 0; i < 8; i++) {
            float2 o2;
            o2.x = __uint_as_float((unsigned)(acc[i][0] & 0xffffffffull))
                 + __uint_as_float((unsigned)(acc[i][0] >> 32));
            o2.y = __uint_as_float((unsigned)(acc[i][1] & 0xffffffffull))
                 + __uint_as_float((unsigned)(acc[i][1] >> 32));
            *(float2*)&xw_s[(p*256 + nb + i)*64 + ob] = o2;
        }
    }
    __syncthreads();                   // xw_s done; union region free for CSR

    // ---- in-degree histogram ----
    if (tid < NV) offs[tid] = 0;
    __syncthreads();
#pragma unroll
    for (int e = tid; e < NE; e += 1024) atomicAdd(&offs[tgte[e]], 1);
    __syncthreads();

    int cnt = 0;
    if (tid < NV) {
        cnt = offs[tid];
        dinv[tid] = rsqrtf((float)(cnt + 1));   // +1 self-loop
    }

    // ---- block exclusive scan over 512 counts (warps 0..15) ----
    int v = cnt;
#pragma unroll
    for (int d = 1; d < 32; d <<= 1) {
        int t = __shfl_up_sync(0xffffffffu, v, d);
        if (lane >= d) v += t;
    }
    if (lane == 31 && wrp < 16) wtmp[wrp] = v;
    __syncthreads();
    if (wrp == 0) {
        int wv = (lane < 16) ? wtmp[lane] : 0;
#pragma unroll
        for (int d = 1; d < 16; d <<= 1) {
            int t = __shfl_up_sync(0xffffffffu, wv, d);
            if (lane >= d) wv += t;
        }
        if (lane < 16) wtmp[lane] = wv;
    }
    __syncthreads();
    if (tid < NV) {
        const int base = (wrp > 0) ? wtmp[wrp-1] : 0;
        const int excl = base + (v - cnt);
        rowptr[tid] = excl;
        offs[tid]   = excl;
        if (tid == 0) rowptr[NV] = NE;
    }
    __syncthreads();

    // ---- scatter packed (nrm, src) edge records sorted by target ----
#pragma unroll
    for (int e = tid; e < NE; e += 1024) {
        int s = srce[e], c = tgte[e];
        int p = atomicAdd(&offs[c], 1);
        float nrm = dinv[s] * dinv[c];
        esh[p] = ((unsigned long long)__float_as_uint(nrm) << 32) | (unsigned)s;
    }
    __syncthreads();

    // ---- gather aggregation: warp per node (16 per warp), lane owns 2 feats ----
    const float bias0 = cbias[2*lane];
    const float bias1 = cbias[2*lane + 1];
    for (int n = wrp*16; n < wrp*16 + 16; n++) {
        const float d = dinv[n];
        float2 xv = *(const float2*)&xw_s[n*FO + 2*lane];
        float a0 = xv.x * (d*d);
        float a1 = xv.y * (d*d);
        int j = rowptr[n];
        const int end = rowptr[n+1];
        for (; j + 4 <= end; j += 4) {
            unsigned long long e0 = esh[j],   e1 = esh[j+1];
            unsigned long long e2 = esh[j+2], e3 = esh[j+3];
            float2 m0 = *(const float2*)&xw_s[(int)(e0 & 0xffffffffu)*FO + 2*lane];
            float2 m1 = *(const float2*)&xw_s[(int)(e1 & 0xffffffffu)*FO + 2*lane];
            float2 m2 = *(const float2*)&xw_s[(int)(e2 & 0xffffffffu)*FO + 2*lane];
            float2 m3 = *(const float2*)&xw_s[(int)(e3 & 0xffffffffu)*FO + 2*lane];
            float w0 = __uint_as_float((unsigned)(e0 >> 32));
            float w1 = __uint_as_float((unsigned)(e1 >> 32));
            float w2 = __uint_as_float((unsigned)(e2 >> 32));
            float w3 = __uint_as_float((unsigned)(e3 >> 32));
            a0 = fmaf(m0.x, w0, a0);  a1 = fmaf(m0.y, w0, a1);
            a0 = fmaf(m1.x, w1, a0);  a1 = fmaf(m1.y, w1, a1);
            a0 = fmaf(m2.x, w2, a0);  a1 = fmaf(m2.y, w2, a1);
            a0 = fmaf(m3.x, w3, a0);  a1 = fmaf(m3.y, w3, a1);
        }
        for (; j < end; j++) {
            unsigned long long e0 = esh[j];
            float2 m = *(const float2*)&xw_s[(int)(e0 & 0xffffffffu)*FO + 2*lane];
            float w = __uint_as_float((unsigned)(e0 >> 32));
            a0 = fmaf(m.x, w, a0);
            a1 = fmaf(m.y, w, a1);
        }
        float2 o;
        o.x = fmaxf(a0 + bias0, 0.f);
        o.y = fmaxf(a1 + bias1, 0.f);
        *(float2*)&g_h[((size_t)g*NV + n)*FO + 2*lane] = o;
    }
}

// =====================================================================================
// K3: logits split-K, weight-stationary (R7 config: grid(8,64), 32 graphs/CTA),
// now with 2-graph interleaved accumulators for 2x MLP on the g_h loads.
// =====================================================================================
__global__ __launch_bounds__(256) void k_lin(const float* __restrict__ lw) {
    const int bx = blockIdx.x;           // 8 graph tiles of 32
    const int by = blockIdx.y;           // k-chunk of 512
    const int tid = threadIdx.x;
    const int lane = tid & 31, wrp = tid >> 5;
    const int c  = lane & 15;
    const int kh = lane >> 4;
    const int kbase = by*512 + wrp*64 + kh*32;
    const int seg = by*8 + wrp;

    unsigned long long wreg[16];
    const float* wp = lw + (size_t)c*KFLAT + kbase;
#pragma unroll
    for (int p = 0; p < 16; p++)
        wreg[p] = *(const unsigned long long*)&wp[2*p];

    for (int gi = 0; gi < 32; gi += 2) {
        const int gA = bx*32 + gi;
        const float* hpA = g_h + (size_t)gA*KFLAT + kbase;
        const float* hpB = hpA + KFLAT;
        unsigned long long aA0 = 0ull, aA1 = 0ull, aB0 = 0ull, aB1 = 0ull;
#pragma unroll
        for (int p = 0; p < 4; p++) {
            ulonglong2 hA0 = *(const ulonglong2*)&hpA[8*p];
            ulonglong2 hB0 = *(const ulonglong2*)&hpB[8*p];
            ulonglong2 hA1 = *(const ulonglong2*)&hpA[8*p + 4];
            ulonglong2 hB1 = *(const ulonglong2*)&hpB[8*p + 4];
            FMA2(aA0, hA0.x, wreg[4*p    ]);
            FMA2(aB0, hB0.x, wreg[4*p    ]);
            FMA2(aA1, hA0.y, wreg[4*p + 1]);
            FMA2(aB1, hB0.y, wreg[4*p + 1]);
            FMA2(aA0, hA1.x, wreg[4*p + 2]);
            FMA2(aB0, hB1.x, wreg[4*p + 2]);
            FMA2(aA1, hA1.y, wreg[4*p + 3]);
            FMA2(aB1, hB1.y, wreg[4*p + 3]);
        }
        float sA = __uint_as_float((unsigned)(aA0 & 0xffffffffull))
                 + __uint_as_float((unsigned)(aA0 >> 32))
                 + __uint_as_float((unsigned)(aA1 & 0xffffffffull))
                 + __uint_as_float((unsigned)(aA1 >> 32));
        float sB = __uint_as_float((unsigned)(aB0 & 0xffffffffull))
                 + __uint_as_float((unsigned)(aB0 >> 32))
                 + __uint_as_float((unsigned)(aB1 & 0xffffffffull))
                 + __uint_as_float((unsigned)(aB1 >> 32));
        sA += __shfl_xor_sync(0xffffffffu, sA, 16);
        sB += __shfl_xor_sync(0xffffffffu, sB, 16);
        if (kh == 0) {
            g_part[((size_t)gA*512 + seg)*NC + c]       = sA;
            g_part[((size_t)(gA+1)*512 + seg)*NC + c]   = sB;
        }
    }
}

// =====================================================================================
// K4: one block per graph. float4 partial sums, smem tree, + bias, log_softmax.
// =====================================================================================
__global__ __launch_bounds__(256) void k_sm(const float* __restrict__ lbias,
                                            float* __restrict__ out) {
    __shared__ float red[64][16];
    const int g = blockIdx.x;
    const int t = threadIdx.x;
    const int quad = t & 3, sg = t >> 2;

    const float4* pp4 = (const float4*)(g_part + (size_t)g*512*NC);
    float4 acc = make_float4(0.f, 0.f, 0.f, 0.f);
#pragma unroll
    for (int s8 = 0; s8 < 8; s8++) {
        float4 v = pp4[(sg*8 + s8)*4 + quad];
        acc.x += v.x; acc.y += v.y; acc.z += v.z; acc.w += v.w;
    }
    *(float4*)&red[sg][quad*4] = acc;
    __syncthreads();

    if (t < 16) {
        float tot = lbias[t];
#pragma unroll 8
        for (int s = 0; s < 64; s++) tot += red[s][t];

        float m = tot;
#pragma unroll
        for (int d = 8; d >= 1; d >>= 1)
            m = fmaxf(m, __shfl_xor_sync(0x0000ffffu, m, d));
        float e = expf(tot - m);
#pragma unroll
        for (int d = 8; d >= 1; d >>= 1)
            e += __shfl_xor_sync(0x0000ffffu, e, d);

        out[(size_t)g*NC + t] = (tot - m) - logf(e);
    }
}

// =====================================================================================
extern "C" void kernel_launch(void* const* d_in, const int* in_sizes, int n_in,
                              void* d_out, int out_size) {
    const float* x  = (const float*)d_in[0];   // [G,NV,FI]
    const int*   ei = (const int*)  d_in[1];   // [G,2,NE]
    const float* cw = (const float*)d_in[2];   // [FO,FI]
    const float* cb = (const float*)d_in[3];   // [FO]
    const float* lw = (const float*)d_in[4];   // [NC,KFLAT]
    const float* lb = (const float*)d_in[5];   // [NC]
    float* out = (float*)d_out;                // [G,NC]

    (void)in_sizes; (void)n_in; (void)out_size;

    cudaFuncSetAttribute(k_fused, cudaFuncAttributeMaxDynamicSharedMemorySize, SMEM_TOT);

    k_fused<<<G, 1024, SMEM_TOT>>>(x, cw, ei, cb);
    k_lin  <<<dim3(8, 64), 256>>>(lw);
    k_sm   <<<G, 256>>>(lb, out);
}

// round 17
// speedup vs baseline: 1.6286x; 1.0075x over previous
#include <cuda_runtime.h>
#include <cstdint>

#define G  256
#define NV 512
#define NE 4096
#define FI 64
#define FO 64
#define NC 16
#define KFLAT (NV*FO)      // 32768

__device__ float g_h [(size_t)G*NV*FO];          // 33.5 MB
__device__ float g_part[(size_t)G*64*NC];        // 1 MB: [g][by 0..63][c]

#define FMA2(acc, a, b) asm("fma.rn.f32x2 %0, %1, %2, %0;" : "+l"(acc) : "l"(a), "l"(b))

// ---- fused-kernel smem layout (bytes) ----------------------------------------------
#define SM_XW    0                          // float[NV*FO]   131072
#define SM_W     (SM_XW   + NV*FO*4)        // float[FO*FI]    16384
#define SM_DINV  (SM_W    + FO*FI*4)        // float[NV]        2048
#define SM_ROWP  (SM_DINV + NV*4)           // int[NV+1]        2052
#define SM_WTMP  ((SM_ROWP + (NV+1)*4 + 15) & ~15)   // int[16]
#define SM_UNION ((SM_WTMP + 64 + 15) & ~15)
#define SM_XSTG  SM_UNION                   // float[256*FI]   65536 (GEMM phase)
#define SM_OFFS  SM_UNION                   // int[NV]          2048 (CSR phase)
#define SM_ESH   ((SM_OFFS + NV*4 + 7) & ~7)// ull[NE]         32768 (packed nrm|src)
#define SMEM_TOT (SM_UNION + 256*FI*4)      // ~217 KB

// =====================================================================================
// Fused per-graph kernel, 1024 threads — FROZEN R15 structure (+ L2 edge prefetch).
// =====================================================================================
__global__ __launch_bounds__(1024, 1) void k_fused(const float* __restrict__ x,
                                                   const float* __restrict__ W,
                                                   const int* __restrict__ eidx,
                                                   const float* __restrict__ cbias) {
    extern __shared__ char sm[];
    float* xw_s  = (float*)(sm + SM_XW);
    float* w_s   = (float*)(sm + SM_W);
    float* dinv  = (float*)(sm + SM_DINV);
    int*   rowptr= (int*)  (sm + SM_ROWP);
    int*   wtmp  = (int*)  (sm + SM_WTMP);
    float* xstg  = (float*)(sm + SM_XSTG);
    int*   offs  = (int*)  (sm + SM_OFFS);
    unsigned long long* esh = (unsigned long long*)(sm + SM_ESH);

    const int g    = blockIdx.x;
    const int tid  = threadIdx.x;
    const int lane = tid & 31, wrp = tid >> 5;
    const int* srce = eidx + (size_t)g*2*NE;
    const int* tgte = srce + NE;

    // ---- L2 prefetch of edge arrays (latency priming for histogram/scatter) ----
    {
        const char* pb = (const char*)srce;        // 32 KB = 256 x 128B lines
        int off = tid * 128;
        if (off < 2*NE*4)
            asm volatile("prefetch.global.L2 [%0];" :: "l"(pb + off));
    }

    // ---- load W with pair-granular XOR swizzle ----
    for (int i = tid; i < FO*FI/2; i += 1024) {
        int o  = i >> 5;
        int fp = (i & 31) * 2;
        int fs = fp ^ (2*((o >> 1) & 15));
        *(unsigned long long*)&w_s[o*64 + fs] =
            *(const unsigned long long*)&W[o*64 + fp];
    }

    // ---- GEMM: 2 phases of 256 nodes ----
    const int tx = tid & 31;          // o-group (2 outs)
    const int ny = tid >> 5;          // n-group (8 rows) == warp id -> a broadcast
    const int nb = ny * 8, ob = tx * 2, sw = 2 * (tx & 15);

#pragma unroll 1
    for (int p = 0; p < 2; p++) {
        __syncthreads();              // union/xstg reuse boundary
        const float4* xg4 = (const float4*)(x + ((size_t)g*NV + p*256) * FI);
        float4* xs4 = (float4*)xstg;
        for (int i = tid; i < 256*FI/4; i += 1024) xs4[i] = xg4[i];
        __syncthreads();

        unsigned long long acc[8][2];
#pragma unroll
        for (int i = 0; i < 8; i++) { acc[i][0] = 0ull; acc[i][1] = 0ull; }

#pragma unroll
        for (int f = 0; f < 64; f += 4) {
            unsigned long long b0[2], b1[2];
#pragma unroll
            for (int j = 0; j < 2; j++) {
                b0[j] = *(const unsigned long long*)&w_s[(ob+j)*64 + ( f      ^ sw)];
                b1[j] = *(const unsigned long long*)&w_s[(ob+j)*64 + ((f + 2) ^ sw)];
            }
#pragma unroll
            for (int i = 0; i < 8; i++) {
                ulonglong2 a2 = *(const ulonglong2*)&xstg[(nb+i)*64 + f];
                FMA2(acc[i][0], a2.x, b0[0]);
                FMA2(acc[i][1], a2.x, b0[1]);
                FMA2(acc[i][0], a2.y, b1[0]);
                FMA2(acc[i][1], a2.y, b1[1]);
            }
        }
#pragma unroll
        for (int i = 0; i < 8; i++) {
            float2 o2;
            o2.x = __uint_as_float((unsigned)(acc[i][0] & 0xffffffffull))
                 + __uint_as_float((unsigned)(acc[i][0] >> 32));
            o2.y = __uint_as_float((unsigned)(acc[i][1] & 0xffffffffull))
                 + __uint_as_float((unsigned)(acc[i][1] >> 32));
            *(float2*)&xw_s[(p*256 + nb + i)*64 + ob] = o2;
        }
    }
    __syncthreads();                   // xw_s done; union region free for CSR

    // ---- in-degree histogram ----
    if (tid < NV) offs[tid] = 0;
    __syncthreads();
#pragma unroll
    for (int e = tid; e < NE; e += 1024) atomicAdd(&offs[tgte[e]], 1);
    __syncthreads();

    int cnt = 0;
    if (tid < NV) {
        cnt = offs[tid];
        dinv[tid] = rsqrtf((float)(cnt + 1));   // +1 self-loop
    }

    // ---- block exclusive scan over 512 counts (warps 0..15) ----
    int v = cnt;
#pragma unroll
    for (int d = 1; d < 32; d <<= 1) {
        int t = __shfl_up_sync(0xffffffffu, v, d);
        if (lane >= d) v += t;
    }
    if (lane == 31 && wrp < 16) wtmp[wrp] = v;
    __syncthreads();
    if (wrp == 0) {
        int wv = (lane < 16) ? wtmp[lane] : 0;
#pragma unroll
        for (int d = 1; d < 16; d <<= 1) {
            int t = __shfl_up_sync(0xffffffffu, wv, d);
            if (lane >= d) wv += t;
        }
        if (lane < 16) wtmp[lane] = wv;
    }
    __syncthreads();
    if (tid < NV) {
        const int base = (wrp > 0) ? wtmp[wrp-1] : 0;
        const int excl = base + (v - cnt);
        rowptr[tid] = excl;
        offs[tid]   = excl;
        if (tid == 0) rowptr[NV] = NE;
    }
    __syncthreads();

    // ---- scatter packed (nrm, src) edge records sorted by target ----
#pragma unroll
    for (int e = tid; e < NE; e += 1024) {
        int s = srce[e], c = tgte[e];
        int p = atomicAdd(&offs[c], 1);
        float nrm = dinv[s] * dinv[c];
        esh[p] = ((unsigned long long)__float_as_uint(nrm) << 32) | (unsigned)s;
    }
    __syncthreads();

    // ---- gather aggregation: warp per node (16 per warp), lane owns 2 feats ----
    const float bias0 = cbias[2*lane];
    const float bias1 = cbias[2*lane + 1];
    for (int n = wrp*16; n < wrp*16 + 16; n++) {
        const float d = dinv[n];
        float2 xv = *(const float2*)&xw_s[n*FO + 2*lane];
        float a0 = xv.x * (d*d);
        float a1 = xv.y * (d*d);
        int j = rowptr[n];
        const int end = rowptr[n+1];
        for (; j + 4 <= end; j += 4) {
            unsigned long long e0 = esh[j],   e1 = esh[j+1];
            unsigned long long e2 = esh[j+2], e3 = esh[j+3];
            float2 m0 = *(const float2*)&xw_s[(int)(e0 & 0xffffffffu)*FO + 2*lane];
            float2 m1 = *(const float2*)&xw_s[(int)(e1 & 0xffffffffu)*FO + 2*lane];
            float2 m2 = *(const float2*)&xw_s[(int)(e2 & 0xffffffffu)*FO + 2*lane];
            float2 m3 = *(const float2*)&xw_s[(int)(e3 & 0xffffffffu)*FO + 2*lane];
            float w0 = __uint_as_float((unsigned)(e0 >> 32));
            float w1 = __uint_as_float((unsigned)(e1 >> 32));
            float w2 = __uint_as_float((unsigned)(e2 >> 32));
            float w3 = __uint_as_float((unsigned)(e3 >> 32));
            a0 = fmaf(m0.x, w0, a0);  a1 = fmaf(m0.y, w0, a1);
            a0 = fmaf(m1.x, w1, a0);  a1 = fmaf(m1.y, w1, a1);
            a0 = fmaf(m2.x, w2, a0);  a1 = fmaf(m2.y, w2, a1);
            a0 = fmaf(m3.x, w3, a0);  a1 = fmaf(m3.y, w3, a1);
        }
        for (; j < end; j++) {
            unsigned long long e0 = esh[j];
            float2 m = *(const float2*)&xw_s[(int)(e0 & 0xffffffffu)*FO + 2*lane];
            float w = __uint_as_float((unsigned)(e0 >> 32));
            a0 = fmaf(m.x, w, a0);
            a1 = fmaf(m.y, w, a1);
        }
        float2 o;
        o.x = fmaxf(a0 + bias0, 0.f);
        o.y = fmaxf(a1 + bias1, 0.f);
        *(float2*)&g_h[((size_t)g*NV + n)*FO + 2*lane] = o;
    }
}

// =====================================================================================
// K3: logits split-K, weight-stationary. grid(8,64), 256 thr. Warp w owns k-seg
// by*512+w*64; 4-graph interleave (16 LDG.128 in flight); per-warp partials reduced
// ACROSS the 8 warps in smem (1 barrier) -> g_part[g][by][c] (64 segs, 1 MB total).
// Deterministic: fixed warp order, fixed by order.
// =====================================================================================
__global__ __launch_bounds__(256) void k_lin(const float* __restrict__ lw) {
    __shared__ float red[32][8][16];     // [g_local][warp][c]
    const int bx = blockIdx.x;           // 8 graph tiles of 32
    const int by = blockIdx.y;           // k-chunk of 512
    const int tid = threadIdx.x;
    const int lane = tid & 31, wrp = tid >> 5;
    const int c  = lane & 15;
    const int kh = lane >> 4;
    const int kbase = by*512 + wrp*64 + kh*32;

    unsigned long long wreg[16];
    const float* wp = lw + (size_t)c*KFLAT + kbase;
#pragma unroll
    for (int p = 0; p < 16; p++)
        wreg[p] = *(const unsigned long long*)&wp[2*p];

#pragma unroll 1
    for (int gi = 0; gi < 32; gi += 4) {
        const float* hp = g_h + (size_t)(bx*32 + gi)*KFLAT + kbase;
        unsigned long long a0 = 0ull, a1 = 0ull, a2 = 0ull, a3 = 0ull;
#pragma unroll
        for (int p = 0; p < 4; p++) {
            ulonglong2 hA = *(const ulonglong2*)&hp[0*KFLAT + 8*p];
            ulonglong2 hB = *(const ulonglong2*)&hp[1*KFLAT + 8*p];
            ulonglong2 hC = *(const ulonglong2*)&hp[2*KFLAT + 8*p];
            ulonglong2 hD = *(const ulonglong2*)&hp[3*KFLAT + 8*p];
            ulonglong2 hA2 = *(const ulonglong2*)&hp[0*KFLAT + 8*p + 4];
            ulonglong2 hB2 = *(const ulonglong2*)&hp[1*KFLAT + 8*p + 4];
            ulonglong2 hC2 = *(const ulonglong2*)&hp[2*KFLAT + 8*p + 4];
            ulonglong2 hD2 = *(const ulonglong2*)&hp[3*KFLAT + 8*p + 4];
            FMA2(a0, hA.x,  wreg[4*p    ]);  FMA2(a1, hB.x,  wreg[4*p    ]);
            FMA2(a2, hC.x,  wreg[4*p    ]);  FMA2(a3, hD.x,  wreg[4*p    ]);
            FMA2(a0, hA.y,  wreg[4*p + 1]);  FMA2(a1, hB.y,  wreg[4*p + 1]);
            FMA2(a2, hC.y,  wreg[4*p + 1]);  FMA2(a3, hD.y,  wreg[4*p + 1]);
            FMA2(a0, hA2.x, wreg[4*p + 2]);  FMA2(a1, hB2.x, wreg[4*p + 2]);
            FMA2(a2, hC2.x, wreg[4*p + 2]);  FMA2(a3, hD2.x, wreg[4*p + 2]);
            FMA2(a0, hA2.y, wreg[4*p + 3]);  FMA2(a1, hB2.y, wreg[4*p + 3]);
            FMA2(a2, hC2.y, wreg[4*p + 3]);  FMA2(a3, hD2.y, wreg[4*p + 3]);
        }
        float s0 = __uint_as_float((unsigned)(a0 & 0xffffffffull)) + __uint_as_float((unsigned)(a0 >> 32));
        float s1 = __uint_as_float((unsigned)(a1 & 0xffffffffull)) + __uint_as_float((unsigned)(a1 >> 32));
        float s2 = __uint_as_float((unsigned)(a2 & 0xffffffffull)) + __uint_as_float((unsigned)(a2 >> 32));
        float s3 = __uint_as_float((unsigned)(a3 & 0xffffffffull)) + __uint_as_float((unsigned)(a3 >> 32));
        s0 += __shfl_xor_sync(0xffffffffu, s0, 16);
        s1 += __shfl_xor_sync(0xffffffffu, s1, 16);
        s2 += __shfl_xor_sync(0xffffffffu, s2, 16);
        s3 += __shfl_xor_sync(0xffffffffu, s3, 16);
        if (kh == 0) {
            red[gi  ][wrp][c] = s0;
            red[gi+1][wrp][c] = s1;
            red[gi+2][wrp][c] = s2;
            red[gi+3][wrp][c] = s3;
        }
    }
    __syncthreads();

    // final cross-warp reduction: 512 (g_local, c) pairs over 256 threads
#pragma unroll
    for (int q = 0; q < 2; q++) {
        int idx = tid + q*256;
        int gl = idx >> 4, cc = idx & 15;
        float s = red[gl][0][cc];
#pragma unroll
        for (int w = 1; w < 8; w++) s += red[gl][w][cc];
        g_part[((size_t)(bx*32 + gl)*64 + by)*NC + cc] = s;
    }
}

// =====================================================================================
// K4: one block per graph. 64 segs x 16 c = 4 KB; 1 float4/thread, smem tree,
// + bias, log_softmax via 16-lane shfl.
// =====================================================================================
__global__ __launch_bounds__(256) void k_sm(const float* __restrict__ lbias,
                                            float* __restrict__ out) {
    __shared__ float red[64][16];
    const int g = blockIdx.x;
    const int t = threadIdx.x;
    const int quad = t & 3, sg = t >> 2;

    const float4* pp4 = (const float4*)(g_part + (size_t)g*64*NC);
    float4 v = pp4[sg*4 + quad];
    *(float4*)&red[sg][quad*4] = v;
    __syncthreads();

    if (t < 16) {
        float tot = lbias[t];
#pragma unroll 8
        for (int s = 0; s < 64; s++) tot += red[s][t];

        float m = tot;
#pragma unroll
        for (int d = 8; d >= 1; d >>= 1)
            m = fmaxf(m, __shfl_xor_sync(0x0000ffffu, m, d));
        float e = expf(tot - m);
#pragma unroll
        for (int d = 8; d >= 1; d >>= 1)
            e += __shfl_xor_sync(0x0000ffffu, e, d);

        out[(size_t)g*NC + t] = (tot - m) - logf(e);
    }
}

// =====================================================================================
extern "C" void kernel_launch(void* const* d_in, const int* in_sizes, int n_in,
                              void* d_out, int out_size) {
    const float* x  = (const float*)d_in[0];   // [G,NV,FI]
    const int*   ei = (const int*)  d_in[1];   // [G,2,NE]
    const float* cw = (const float*)d_in[2];   // [FO,FI]
    const float* cb = (const float*)d_in[3];   // [FO]
    const float* lw = (const float*)d_in[4];   // [NC,KFLAT]
    const float* lb = (const float*)d_in[5];   // [NC]
    float* out = (float*)d_out;                // [G,NC]

    (void)in_sizes; (void)n_in; (void)out_size;

    cudaFuncSetAttribute(k_fused, cudaFuncAttributeMaxDynamicSharedMemorySize, SMEM_TOT);

    k_fused<<<G, 1024, SMEM_TOT>>>(x, cw, ei, cb);
    k_lin  <<<dim3(8, 64), 256>>>(lw);
    k_sm   <<<G, 256>>>(lb, out);
}